// round 7
// baseline (speedup 1.0000x reference)
#include <cuda_runtime.h>
#include <math.h>
#include <stdint.h>

#define T      4096
#define H      1024
#define IDIM   512
#define E      64
#define TOPK   2
#define TMTOK  64
#define NTILES 192
#define PPOS   (T*TOPK + E*TMTOK)

// ---------------- device scratch ----------------
__device__ int   g_off[E+1];
__device__ int   g_tile_off[E+1];
__device__ int   g_perm[PPOS];
__device__ float g_pw[PPOS];
__device__ int   g_sel[T*TOPK];
__device__ float g_w[T*TOPK];
__device__ int   g_ypos[T*TOPK];
__device__ uint2 g_xhi[(T+1)*H/4],   g_xlo[(T+1)*H/4];
__device__ uint2 g_w1hi[E*IDIM*H/4], g_w1lo[E*IDIM*H/4];
__device__ uint2 g_w3hi[E*IDIM*H/4], g_w3lo[E*IDIM*H/4];
__device__ uint2 g_w2hi[E*H*IDIM/4], g_w2lo[E*H*IDIM/4];
__device__ uint32_t g_ahi32[NTILES*TMTOK*IDIM/2], g_alo32[NTILES*TMTOK*IDIM/2];
__device__ float g_y[(size_t)NTILES*TMTOK*H];

// ---------------- helpers ----------------
__device__ __forceinline__ uint32_t smem_u32(const void* p) {
    uint32_t a;
    asm("{ .reg .u64 t; cvta.to.shared.u64 t, %1; cvt.u32.u64 %0, t; }" : "=r"(a) : "l"(p));
    return a;
}
__device__ __forceinline__ void cpa16(uint32_t dst, const void* src) {
    asm volatile("cp.async.cg.shared.global [%0], [%1], 16;" :: "r"(dst), "l"(src) : "memory");
}
#define CP_COMMIT() asm volatile("cp.async.commit_group;" ::: "memory")
#define CP_WAIT(n)  asm volatile("cp.async.wait_group %0;" :: "n"(n) : "memory")

__device__ __forceinline__ void ldm4(uint32_t* r, uint32_t addr) {
    asm volatile("ldmatrix.sync.aligned.m8n8.x4.shared.b16 {%0,%1,%2,%3}, [%4];"
        : "=r"(r[0]), "=r"(r[1]), "=r"(r[2]), "=r"(r[3]) : "r"(addr));
}
__device__ __forceinline__ void mma16(float* d, const uint32_t* a, uint32_t b0, uint32_t b1) {
    asm volatile("mma.sync.aligned.m16n8k16.row.col.f32.bf16.bf16.f32 "
        "{%0,%1,%2,%3}, {%4,%5,%6,%7}, {%8,%9}, {%0,%1,%2,%3};"
        : "+f"(d[0]), "+f"(d[1]), "+f"(d[2]), "+f"(d[3])
        : "r"(a[0]), "r"(a[1]), "r"(a[2]), "r"(a[3]), "r"(b0), "r"(b1));
}
__device__ __forceinline__ void split2(float a, float b, uint32_t& hi, uint32_t& lo) {
    uint32_t h;
    asm("cvt.rn.bf16x2.f32 %0, %1, %2;" : "=r"(h) : "f"(b), "f"(a));
    float ra = a - __uint_as_float(h << 16);
    float rb = b - __uint_as_float(h & 0xffff0000u);
    asm("cvt.rn.bf16x2.f32 %0, %1, %2;" : "=r"(lo) : "f"(rb), "f"(ra));
    hi = h;
}

// ---------------- convert fp32 -> bf16 hi/lo ----------------
#define X4   (T*H/4)
#define W14  (E*IDIM*H/4)
#define TOT4 (X4 + 3*W14)
__global__ void k_cvt(const float* __restrict__ x, const float* __restrict__ W1,
                      const float* __restrict__ W2, const float* __restrict__ W3) {
    size_t gid = (size_t)blockIdx.x * blockDim.x + threadIdx.x;
    size_t stride = (size_t)gridDim.x * blockDim.x;
    if (gid < H/4) { g_xhi[(size_t)T*H/4 + gid] = make_uint2(0,0); g_xlo[(size_t)T*H/4 + gid] = make_uint2(0,0); }
    for (size_t i = gid; i < TOT4; i += stride) {
        const float4* s; uint2 *dh, *dl; size_t j = i;
        if (j < X4)            { s = (const float4*)x;  dh = g_xhi;  dl = g_xlo; }
        else { j -= X4;
            if (j < W14)       { s = (const float4*)W1; dh = g_w1hi; dl = g_w1lo; }
            else { j -= W14;
                if (j < W14)   { s = (const float4*)W3; dh = g_w3hi; dl = g_w3lo; }
                else { j -= W14; s = (const float4*)W2; dh = g_w2hi; dl = g_w2lo; } } }
        float4 v = s[j];
        uint32_t h0,l0,h1,l1;
        split2(v.x, v.y, h0, l0);
        split2(v.z, v.w, h1, l1);
        dh[j] = make_uint2(h0, h1);
        dl[j] = make_uint2(l0, l1);
    }
}

// ---------------- router (16 tokens / block) ----------------
__global__ void __launch_bounds__(256) k_router(const float* __restrict__ x,
                                                const float* __restrict__ gw,
                                                const float* __restrict__ gb) {
    extern __shared__ float rsm[];
    float* xs  = rsm;
    float* red = rsm + 16384;
    float* lg  = red + 4096;
    const int t0 = blockIdx.x * 16;
    const int tid = threadIdx.x;
    float4* xs4 = (float4*)xs;
    const float4* xg = (const float4*)(x + (size_t)t0 * H);
    for (int i = tid; i < 16 * H / 4; i += 256) xs4[i] = xg[i];
    __syncthreads();
    const int e = tid & 63, ck = tid >> 6;
    const float4* gwp = (const float4*)(gw + (size_t)e * H + ck * 256);
    float acc[16];
#pragma unroll
    for (int r = 0; r < 16; r++) acc[r] = 0.f;
    for (int j = 0; j < 64; j++) {
        float4 wv = gwp[j];
#pragma unroll
        for (int r = 0; r < 16; r++) {
            float4 xv = xs4[r * 256 + ck * 64 + j];
            acc[r] += xv.x * wv.x + xv.y * wv.y + xv.z * wv.z + xv.w * wv.w;
        }
    }
#pragma unroll
    for (int r = 0; r < 16; r++) red[tid * 16 + r] = acc[r];
    __syncthreads();
    if (tid < 64) {
#pragma unroll
        for (int r = 0; r < 16; r++)
            lg[r * 64 + tid] = red[tid * 16 + r] + red[(tid + 64) * 16 + r] +
                               red[(tid + 128) * 16 + r] + red[(tid + 192) * 16 + r] + gb[tid];
    }
    __syncthreads();
    if (tid < 16) {
        int t = t0 + tid;
        float l0 = -1e30f, l1 = -1e30f;
        int e0 = 0, e1 = 0;
        for (int k = 0; k < E; k++) {
            float l = lg[tid * 64 + k];
            if (l > l0)      { l1 = l0; e1 = e0; l0 = l; e0 = k; }
            else if (l > l1) { l1 = l;  e1 = k; }
        }
        float rr = expf(l1 - l0);
        float w0 = 1.f / (1.f + rr);
        float w1 = rr * w0;
        g_sel[2 * t] = e0;  g_sel[2 * t + 1] = e1;
        g_w[2 * t]   = w0;  g_w[2 * t + 1]   = w1;
    }
}

// ---------------- aux: histogram + scan + pad + scatter ----------------
__global__ void __launch_bounds__(256) k_aux() {
    __shared__ int hist[E];
    __shared__ int soff[E+1], stoff[E+1];
    __shared__ int cur[E];
    const int tid = threadIdx.x;
    if (tid < E) hist[tid] = 0;
    __syncthreads();
    for (int i = tid; i < T * TOPK; i += 256) atomicAdd(&hist[g_sel[i]], 1);
    __syncthreads();
    if (tid == 0) {
        int off = 0, toff = 0;
        for (int e = 0; e < E; e++) {
            soff[e] = off; stoff[e] = toff;
            int tiles = (hist[e] + TMTOK - 1) / TMTOK;
            off += tiles * TMTOK; toff += tiles;
        }
        soff[E] = off; stoff[E] = toff;
    }
    __syncthreads();
    if (tid < E) { cur[tid] = soff[tid]; g_off[tid] = soff[tid]; g_tile_off[tid] = stoff[tid]; }
    if (tid == 0) { g_off[E] = soff[E]; g_tile_off[E] = stoff[E]; }
    for (int i = tid; i < PPOS; i += 256) g_perm[i] = -1;
    __syncthreads();
    for (int i = tid; i < T * TOPK; i += 256) {
        int e = g_sel[i];
        int pos = atomicAdd(&cur[e], 1);
        g_perm[pos] = i >> 1;
        g_pw[pos] = g_w[i];
        int local = pos - soff[e];
        g_ypos[i] = (stoff[e] + (local >> 6)) * TMTOK + (local & 63);
    }
}

// ---------------- FFN: 256 threads, 3 CTAs/SM, KC=32, 2-stage ----------------
#define KC      32
#define RSTRIDE 80
#define STAGE   (384*RSTRIDE)     // 30720 B
#define SMEM_REQ (2*STAGE)        // 61440 B

__device__ __forceinline__ uint32_t adr(uint32_t buf, int rowbase, int ks, int lane) {
    return buf + (uint32_t)(rowbase + (lane & 15)) * RSTRIDE + (uint32_t)(ks * 2 + (lane >> 4)) * 16;
}

// stage rows (64B each): [0,64)xhi [64,128)xlo [128,192)w1h [192,256)w1l [256,320)w3h [320,384)w3l
__device__ __forceinline__ void ld1row(uint32_t buf, const int* s_tok, int e, int ic, int k, int row) {
    const char* src;
    if (row < 128) {
        int tok = s_tok[row & 63];
        if (tok < 0) tok = T;
        const char* base = (row < 64) ? (const char*)g_xhi : (const char*)g_xlo;
        src = base + (size_t)tok * (H * 2) + k * (KC * 2);
    } else {
        int n = row & 63;
        int sel = (row - 128) >> 6;
        const char* base = (sel == 0) ? (const char*)g_w1hi :
                           (sel == 1) ? (const char*)g_w1lo :
                           (sel == 2) ? (const char*)g_w3hi : (const char*)g_w3lo;
        src = base + ((size_t)(e * IDIM + ic * 64 + n)) * (H * 2) + k * (KC * 2);
    }
    uint32_t d = buf + (uint32_t)row * RSTRIDE;
#pragma unroll
    for (int q = 0; q < 4; q++) cpa16(d + q * 16, src + q * 16);
}
__device__ __forceinline__ void ld_g1(uint32_t buf, const int* s_tok, int e, int ic, int k) {
    ld1row(buf, s_tok, e, ic, k, threadIdx.x);
    if (threadIdx.x < 128) ld1row(buf, s_tok, e, ic, k, 256 + threadIdx.x);
}
// stage rows: [0,64)ahi [64,128)alo [128,192)w2h [192,256)w2l
__device__ __forceinline__ void ld_g2(uint32_t buf, int tile, int e, int hc, int k) {
    const int row = threadIdx.x;
    const char* src;
    if (row < 128) {
        const char* base = (row < 64) ? (const char*)g_ahi32 : (const char*)g_alo32;
        src = base + ((size_t)tile * TMTOK + (row & 63)) * (IDIM * 2) + k * (KC * 2);
    } else {
        int n = row & 63;
        const char* base = (row < 192) ? (const char*)g_w2hi : (const char*)g_w2lo;
        src = base + ((size_t)(e * H + hc * 64 + n)) * (IDIM * 2) + k * (KC * 2);
    }
    uint32_t d = buf + (uint32_t)row * RSTRIDE;
#pragma unroll
    for (int q = 0; q < 4; q++) cpa16(d + q * 16, src + q * 16);
}

__global__ void __launch_bounds__(256, 3) k_ffn() {
    const int tile = blockIdx.x;
    if (tile >= g_tile_off[E]) return;
    extern __shared__ char sm[];
    const uint32_t sb = smem_u32(sm);
    __shared__ int   s_tok[TMTOK];
    __shared__ float s_w[TMTOK];

    const int tid = threadIdx.x, lane = tid & 31, wid = tid >> 5;
    const int wm = wid & 1, wn = wid >> 1;     // 2(M) x 4(N) warp grid: M32 x N16 per warp

    int lo = 0, hi = E;
    while (lo + 1 < hi) { int m = (lo + hi) >> 1; if (g_tile_off[m] <= tile) lo = m; else hi = m; }
    const int e = lo;
    const int p0 = g_off[e] + (tile - g_tile_off[e]) * TMTOK;

    if (tid < TMTOK) {
        int tk = g_perm[p0 + tid];
        s_tok[tid] = tk;
        s_w[tid] = (tk >= 0) ? g_pw[p0 + tid] : 0.f;
    }
    __syncthreads();

    const uint32_t bufs[2] = { sb, sb + STAGE };
    const int rbase = wm * 32 + (lane >> 2);

    // ================= GEMM1: h1/h3, 8 I-chunks of 64, K = 32 x KC32 =================
    for (int ic = 0; ic < 8; ic++) {
        ld_g1(bufs[0], s_tok, e, ic, 0); CP_COMMIT();
        float c1[2][2][4], c3[2][2][4];
#pragma unroll
        for (int a = 0; a < 2; a++)
#pragma unroll
            for (int b = 0; b < 2; b++)
#pragma unroll
                for (int c = 0; c < 4; c++) { c1[a][b][c] = 0.f; c3[a][b][c] = 0.f; }

        for (int k = 0; k < 32; k++) {
            CP_WAIT(0);
            __syncthreads();
            if (k + 1 < 32) { ld_g1(bufs[(k + 1) & 1], s_tok, e, ic, k + 1); CP_COMMIT(); }
            uint32_t cb = bufs[k & 1];
#pragma unroll
            for (int ks = 0; ks < 2; ks++) {
                uint32_t ah[2][4], al[2][4];
                ldm4(ah[0], adr(cb, wm * 32,           ks, lane));
                ldm4(ah[1], adr(cb, wm * 32 + 16,      ks, lane));
                ldm4(al[0], adr(cb, 64 + wm * 32,      ks, lane));
                ldm4(al[1], adr(cb, 64 + wm * 32 + 16, ks, lane));
                uint32_t b1h[4], b1l[4], b3h[4], b3l[4];
                ldm4(b1h, adr(cb, 128 + wn * 16, ks, lane));
                ldm4(b1l, adr(cb, 192 + wn * 16, ks, lane));
                ldm4(b3h, adr(cb, 256 + wn * 16, ks, lane));
                ldm4(b3l, adr(cb, 320 + wn * 16, ks, lane));
                // term-major: 8 independent MMAs per term group
#pragma unroll
                for (int nk = 0; nk < 2; nk++)
#pragma unroll
                    for (int mi = 0; mi < 2; mi++) mma16(c1[mi][nk], ah[mi], b1h[nk], b1h[nk + 2]);
#pragma unroll
                for (int nk = 0; nk < 2; nk++)
#pragma unroll
                    for (int mi = 0; mi < 2; mi++) mma16(c3[mi][nk], ah[mi], b3h[nk], b3h[nk + 2]);
#pragma unroll
                for (int nk = 0; nk < 2; nk++)
#pragma unroll
                    for (int mi = 0; mi < 2; mi++) mma16(c1[mi][nk], al[mi], b1h[nk], b1h[nk + 2]);
#pragma unroll
                for (int nk = 0; nk < 2; nk++)
#pragma unroll
                    for (int mi = 0; mi < 2; mi++) mma16(c3[mi][nk], al[mi], b3h[nk], b3h[nk + 2]);
#pragma unroll
                for (int nk = 0; nk < 2; nk++)
#pragma unroll
                    for (int mi = 0; mi < 2; mi++) mma16(c1[mi][nk], ah[mi], b1l[nk], b1l[nk + 2]);
#pragma unroll
                for (int nk = 0; nk < 2; nk++)
#pragma unroll
                    for (int mi = 0; mi < 2; mi++) mma16(c3[mi][nk], ah[mi], b3l[nk], b3l[nk + 2]);
            }
        }
        // epilogue: silu(h1)*h3*w -> bf16 hi/lo scratch
#pragma unroll
        for (int mi = 0; mi < 2; mi++)
#pragma unroll
            for (int nk = 0; nk < 2; nk++)
#pragma unroll
                for (int hf = 0; hf < 2; hf++) {
                    int row = rbase + mi * 16 + hf * 8;
                    int col = ic * 64 + wn * 16 + nk * 8 + ((lane & 3) << 1);
                    float w = s_w[row];
                    float h1a = c1[mi][nk][hf * 2], h1b = c1[mi][nk][hf * 2 + 1];
                    float a0 = h1a / (1.f + __expf(-h1a)) * c3[mi][nk][hf * 2] * w;
                    float a1 = h1b / (1.f + __expf(-h1b)) * c3[mi][nk][hf * 2 + 1] * w;
                    uint32_t hv, lv; split2(a0, a1, hv, lv);
                    size_t o = ((size_t)(tile * TMTOK + row) * IDIM + col) >> 1;
                    g_ahi32[o] = hv; g_alo32[o] = lv;
                }
        __syncthreads();
    }
    __threadfence();
    __syncthreads();

    // ================= GEMM2: y = a @ W2^T, 16 H-chunks of 64, K = 16 x KC32 =================
    for (int hc = 0; hc < 16; hc++) {
        ld_g2(bufs[0], tile, e, hc, 0); CP_COMMIT();
        float cc[2][2][4];
#pragma unroll
        for (int a = 0; a < 2; a++)
#pragma unroll
            for (int b = 0; b < 2; b++)
#pragma unroll
                for (int c = 0; c < 4; c++) cc[a][b][c] = 0.f;

        for (int k = 0; k < 16; k++) {
            CP_WAIT(0);
            __syncthreads();
            if (k + 1 < 16) { ld_g2(bufs[(k + 1) & 1], tile, e, hc, k + 1); CP_COMMIT(); }
            uint32_t cb = bufs[k & 1];
#pragma unroll
            for (int ks = 0; ks < 2; ks++) {
                uint32_t ah[2][4], al[2][4];
                ldm4(ah[0], adr(cb, wm * 32,           ks, lane));
                ldm4(ah[1], adr(cb, wm * 32 + 16,      ks, lane));
                ldm4(al[0], adr(cb, 64 + wm * 32,      ks, lane));
                ldm4(al[1], adr(cb, 64 + wm * 32 + 16, ks, lane));
                uint32_t b2h[4], b2l[4];
                ldm4(b2h, adr(cb, 128 + wn * 16, ks, lane));
                ldm4(b2l, adr(cb, 192 + wn * 16, ks, lane));
#pragma unroll
                for (int nk = 0; nk < 2; nk++)
#pragma unroll
                    for (int mi = 0; mi < 2; mi++) mma16(cc[mi][nk], ah[mi], b2h[nk], b2h[nk + 2]);
#pragma unroll
                for (int nk = 0; nk < 2; nk++)
#pragma unroll
                    for (int mi = 0; mi < 2; mi++) mma16(cc[mi][nk], al[mi], b2h[nk], b2h[nk + 2]);
#pragma unroll
                for (int nk = 0; nk < 2; nk++)
#pragma unroll
                    for (int mi = 0; mi < 2; mi++) mma16(cc[mi][nk], ah[mi], b2l[nk], b2l[nk + 2]);
            }
        }
#pragma unroll
        for (int mi = 0; mi < 2; mi++)
#pragma unroll
            for (int nk = 0; nk < 2; nk++)
#pragma unroll
                for (int hf = 0; hf < 2; hf++) {
                    int row = rbase + mi * 16 + hf * 8;
                    int col = hc * 64 + wn * 16 + nk * 8 + ((lane & 3) << 1);
                    float2 v = make_float2(cc[mi][nk][hf * 2], cc[mi][nk][hf * 2 + 1]);
                    *(float2*)&g_y[(size_t)(tile * TMTOK + row) * H + col] = v;
                }
        __syncthreads();
    }
}

// ---------------- gather ----------------
__global__ void k_gather(float* __restrict__ out) {
    int idx = blockIdx.x * 256 + threadIdx.x;
    if (idx >= T * H / 4) return;
    int t = idx / (H / 4), c = idx % (H / 4);
    int p0 = g_ypos[2 * t], p1 = g_ypos[2 * t + 1];
    float4 a = ((const float4*)g_y)[(size_t)p0 * (H / 4) + c];
    float4 b = ((const float4*)g_y)[(size_t)p1 * (H / 4) + c];
    ((float4*)out)[idx] = make_float4(a.x + b.x, a.y + b.y, a.z + b.z, a.w + b.w);
}

// ---------------- launch ----------------
extern "C" void kernel_launch(void* const* d_in, const int* in_sizes, int n_in,
                              void* d_out, int out_size) {
    const float* x  = (const float*)d_in[0];
    const float* gw = (const float*)d_in[1];
    const float* gb = (const float*)d_in[2];
    const float* W1 = (const float*)d_in[3];
    const float* W2 = (const float*)d_in[4];
    const float* W3 = (const float*)d_in[5];
    float* out = (float*)d_out;

    cudaFuncSetAttribute(k_router, cudaFuncAttributeMaxDynamicSharedMemorySize, 86016);
    cudaFuncSetAttribute(k_ffn,    cudaFuncAttributeMaxDynamicSharedMemorySize, SMEM_REQ);

    k_cvt<<<2048, 256>>>(x, W1, W2, W3);
    k_router<<<T / 16, 256, 86016>>>(x, gw, gb);
    k_aux<<<1, 256>>>();
    k_ffn<<<NTILES, 256, SMEM_REQ>>>();
    k_gather<<<(T * H / 4 + 255) / 256, 256>>>(out);
}

// round 8
// speedup vs baseline: 1.4819x; 1.4819x over previous
#include <cuda_runtime.h>
#include <math.h>
#include <stdint.h>

#define T      4096
#define H      1024
#define IDIM   512
#define E      64
#define TOPK   2
#define TMTOK  128
#define NTILES 128
#define PPOS   (T*TOPK + E*TMTOK)

// ---------------- device scratch ----------------
__device__ int   g_off[E+1];
__device__ int   g_tile_off[E+1];
__device__ int   g_texp[NTILES];     // tile -> expert
__device__ int   g_perm[PPOS];
__device__ float g_pw[PPOS];
__device__ int   g_sel[T*TOPK];
__device__ float g_w[T*TOPK];
__device__ int   g_ypos[T*TOPK];
__device__ uint2 g_xhi[(T+1)*H/4],   g_xlo[(T+1)*H/4];
__device__ uint2 g_w1hi[E*IDIM*H/4], g_w1lo[E*IDIM*H/4];
__device__ uint2 g_w3hi[E*IDIM*H/4], g_w3lo[E*IDIM*H/4];
__device__ uint2 g_w2hi[E*H*IDIM/4], g_w2lo[E*H*IDIM/4];
__device__ uint32_t g_ahi32[NTILES*TMTOK*IDIM/2], g_alo32[NTILES*TMTOK*IDIM/2];
__device__ float g_y[(size_t)NTILES*TMTOK*H];

// ---------------- helpers ----------------
__device__ __forceinline__ uint32_t smem_u32(const void* p) {
    uint32_t a;
    asm("{ .reg .u64 t; cvta.to.shared.u64 t, %1; cvt.u32.u64 %0, t; }" : "=r"(a) : "l"(p));
    return a;
}
__device__ __forceinline__ void cpa16(uint32_t dst, const void* src) {
    asm volatile("cp.async.cg.shared.global [%0], [%1], 16;" :: "r"(dst), "l"(src) : "memory");
}
#define CP_COMMIT() asm volatile("cp.async.commit_group;" ::: "memory")
#define CP_WAIT(n)  asm volatile("cp.async.wait_group %0;" :: "n"(n) : "memory")

__device__ __forceinline__ void ldm4(uint32_t* r, uint32_t addr) {
    asm volatile("ldmatrix.sync.aligned.m8n8.x4.shared.b16 {%0,%1,%2,%3}, [%4];"
        : "=r"(r[0]), "=r"(r[1]), "=r"(r[2]), "=r"(r[3]) : "r"(addr));
}
__device__ __forceinline__ void mma16(float* d, const uint32_t* a, uint32_t b0, uint32_t b1) {
    asm volatile("mma.sync.aligned.m16n8k16.row.col.f32.bf16.bf16.f32 "
        "{%0,%1,%2,%3}, {%4,%5,%6,%7}, {%8,%9}, {%0,%1,%2,%3};"
        : "+f"(d[0]), "+f"(d[1]), "+f"(d[2]), "+f"(d[3])
        : "r"(a[0]), "r"(a[1]), "r"(a[2]), "r"(a[3]), "r"(b0), "r"(b1));
}
__device__ __forceinline__ void split2(float a, float b, uint32_t& hi, uint32_t& lo) {
    uint32_t h;
    asm("cvt.rn.bf16x2.f32 %0, %1, %2;" : "=r"(h) : "f"(b), "f"(a));
    float ra = a - __uint_as_float(h << 16);
    float rb = b - __uint_as_float(h & 0xffff0000u);
    asm("cvt.rn.bf16x2.f32 %0, %1, %2;" : "=r"(lo) : "f"(rb), "f"(ra));
    hi = h;
}

// ---------------- convert fp32 -> bf16 hi/lo ----------------
#define X4   (T*H/4)
#define W14  (E*IDIM*H/4)
#define TOT4 (X4 + 3*W14)
__global__ void k_cvt(const float* __restrict__ x, const float* __restrict__ W1,
                      const float* __restrict__ W2, const float* __restrict__ W3) {
    size_t gid = (size_t)blockIdx.x * blockDim.x + threadIdx.x;
    size_t stride = (size_t)gridDim.x * blockDim.x;
    if (gid < H/4) { g_xhi[(size_t)T*H/4 + gid] = make_uint2(0,0); g_xlo[(size_t)T*H/4 + gid] = make_uint2(0,0); }
    for (size_t i = gid; i < TOT4; i += stride) {
        const float4* s; uint2 *dh, *dl; size_t j = i;
        if (j < X4)            { s = (const float4*)x;  dh = g_xhi;  dl = g_xlo; }
        else { j -= X4;
            if (j < W14)       { s = (const float4*)W1; dh = g_w1hi; dl = g_w1lo; }
            else { j -= W14;
                if (j < W14)   { s = (const float4*)W3; dh = g_w3hi; dl = g_w3lo; }
                else { j -= W14; s = (const float4*)W2; dh = g_w2hi; dl = g_w2lo; } } }
        float4 v = s[j];
        uint32_t h0,l0,h1,l1;
        split2(v.x, v.y, h0, l0);
        split2(v.z, v.w, h1, l1);
        dh[j] = make_uint2(h0, h1);
        dl[j] = make_uint2(l0, l1);
    }
}

// ---------------- router (16 tokens / block) ----------------
__global__ void __launch_bounds__(256) k_router(const float* __restrict__ x,
                                                const float* __restrict__ gw,
                                                const float* __restrict__ gb) {
    extern __shared__ float rsm[];
    float* xs  = rsm;
    float* red = rsm + 16384;
    float* lg  = red + 4096;
    const int t0 = blockIdx.x * 16;
    const int tid = threadIdx.x;
    float4* xs4 = (float4*)xs;
    const float4* xg = (const float4*)(x + (size_t)t0 * H);
    for (int i = tid; i < 16 * H / 4; i += 256) xs4[i] = xg[i];
    __syncthreads();
    const int e = tid & 63, ck = tid >> 6;
    const float4* gwp = (const float4*)(gw + (size_t)e * H + ck * 256);
    float acc[16];
#pragma unroll
    for (int r = 0; r < 16; r++) acc[r] = 0.f;
    for (int j = 0; j < 64; j++) {
        float4 wv = gwp[j];
#pragma unroll
        for (int r = 0; r < 16; r++) {
            float4 xv = xs4[r * 256 + ck * 64 + j];
            acc[r] += xv.x * wv.x + xv.y * wv.y + xv.z * wv.z + xv.w * wv.w;
        }
    }
#pragma unroll
    for (int r = 0; r < 16; r++) red[tid * 16 + r] = acc[r];
    __syncthreads();
    if (tid < 64) {
#pragma unroll
        for (int r = 0; r < 16; r++)
            lg[r * 64 + tid] = red[tid * 16 + r] + red[(tid + 64) * 16 + r] +
                               red[(tid + 128) * 16 + r] + red[(tid + 192) * 16 + r] + gb[tid];
    }
    __syncthreads();
    if (tid < 16) {
        int t = t0 + tid;
        float l0 = -1e30f, l1 = -1e30f;
        int e0 = 0, e1 = 0;
        for (int k = 0; k < E; k++) {
            float l = lg[tid * 64 + k];
            if (l > l0)      { l1 = l0; e1 = e0; l0 = l; e0 = k; }
            else if (l > l1) { l1 = l;  e1 = k; }
        }
        float rr = expf(l1 - l0);
        float w0 = 1.f / (1.f + rr);
        float w1 = rr * w0;
        g_sel[2 * t] = e0;  g_sel[2 * t + 1] = e1;
        g_w[2 * t]   = w0;  g_w[2 * t + 1]   = w1;
    }
}

// ---------------- aux: histogram + scan + pad + scatter ----------------
__global__ void __launch_bounds__(256) k_aux() {
    __shared__ int hist[E];
    __shared__ int soff[E+1], stoff[E+1];
    __shared__ int cur[E];
    const int tid = threadIdx.x;
    if (tid < E) hist[tid] = 0;
    __syncthreads();
    for (int i = tid; i < T * TOPK; i += 256) atomicAdd(&hist[g_sel[i]], 1);
    __syncthreads();
    if (tid == 0) {
        int off = 0, toff = 0;
        for (int e = 0; e < E; e++) {
            soff[e] = off; stoff[e] = toff;
            int tiles = (hist[e] + TMTOK - 1) / TMTOK;
            for (int q = 0; q < tiles; q++) g_texp[toff + q] = e;
            off += tiles * TMTOK; toff += tiles;
        }
        soff[E] = off; stoff[E] = toff;
    }
    __syncthreads();
    if (tid < E) { cur[tid] = soff[tid]; g_off[tid] = soff[tid]; g_tile_off[tid] = stoff[tid]; }
    if (tid == 0) { g_off[E] = soff[E]; g_tile_off[E] = stoff[E]; }
    for (int i = tid; i < PPOS; i += 256) g_perm[i] = -1;
    __syncthreads();
    for (int i = tid; i < T * TOPK; i += 256) {
        int e = g_sel[i];
        int pos = atomicAdd(&cur[e], 1);
        g_perm[pos] = i >> 1;
        g_pw[pos] = g_w[i];
        int local = pos - soff[e];
        g_ypos[i] = (stoff[e] + (local >> 7)) * TMTOK + (local & 127);
    }
}

// ---------------- FFN GEMMs: 2D grid (tile, n-chunk) ----------------
#define KC      32
#define RSTRIDE 80
#define STAGE   (512*RSTRIDE)     // 40960 B
#define SMEM_REQ (2*STAGE)        // 81920 B

__device__ __forceinline__ uint32_t adr(uint32_t buf, int rowbase, int ks, int lane) {
    return buf + (uint32_t)(rowbase + (lane & 15)) * RSTRIDE + (uint32_t)(ks * 2 + (lane >> 4)) * 16;
}

// g1 stage rows (64B): [0,128)xhi [128,256)xlo [256,320)w1h [320,384)w1l [384,448)w3h [448,512)w3l
__device__ __forceinline__ void ld_g1(uint32_t buf, const int* s_tok, int e, int nc, int k) {
    const int tid = threadIdx.x;
#pragma unroll
    for (int j = 0; j < 2; j++) {
        int row = tid + j * 256;
        const char* src;
        if (row < 256) {
            int tok = s_tok[row & 127];
            if (tok < 0) tok = T;
            const char* base = (row < 128) ? (const char*)g_xhi : (const char*)g_xlo;
            src = base + (size_t)tok * (H * 2) + k * (KC * 2);
        } else {
            int n = row & 63;
            int sel = (row - 256) >> 6;
            const char* base = (sel == 0) ? (const char*)g_w1hi :
                               (sel == 1) ? (const char*)g_w1lo :
                               (sel == 2) ? (const char*)g_w3hi : (const char*)g_w3lo;
            src = base + ((size_t)(e * IDIM + nc * 64 + n)) * (H * 2) + k * (KC * 2);
        }
        uint32_t d = buf + (uint32_t)row * RSTRIDE;
#pragma unroll
        for (int q = 0; q < 4; q++) cpa16(d + q * 16, src + q * 16);
    }
}
// g2 stage rows: [0,128)ahi [128,256)alo [256,384)w2h [384,512)w2l
__device__ __forceinline__ void ld_g2(uint32_t buf, int tile, int e, int nc, int k) {
    const int tid = threadIdx.x;
#pragma unroll
    for (int j = 0; j < 2; j++) {
        int row = tid + j * 256;
        const char* src;
        if (row < 256) {
            const char* base = (row < 128) ? (const char*)g_ahi32 : (const char*)g_alo32;
            src = base + ((size_t)tile * TMTOK + (row & 127)) * (IDIM * 2) + k * (KC * 2);
        } else {
            int n = row & 127;
            const char* base = (row < 384) ? (const char*)g_w2hi : (const char*)g_w2lo;
            src = base + ((size_t)(e * H + nc * 128 + n)) * (IDIM * 2) + k * (KC * 2);
        }
        uint32_t d = buf + (uint32_t)row * RSTRIDE;
#pragma unroll
        for (int q = 0; q < 4; q++) cpa16(d + q * 16, src + q * 16);
    }
}

// ---- GEMM1: h1/h3 for I-chunk of 64, silu epilogue. grid (NTILES, 8) ----
__global__ void __launch_bounds__(256, 2) k_g1() {
    const int tile = blockIdx.x;
    if (tile >= g_tile_off[E]) return;
    const int nc = blockIdx.y;
    extern __shared__ char sm[];
    const uint32_t sb = smem_u32(sm);
    __shared__ int   s_tok[TMTOK];
    __shared__ float s_w[TMTOK];

    const int tid = threadIdx.x, lane = tid & 31, wid = tid >> 5;
    const int wm = wid & 3, wn = wid >> 2;   // 4(M) x 2(N): warp M32 x N32

    const int e = g_texp[tile];
    const int p0 = g_off[e] + (tile - g_tile_off[e]) * TMTOK;

    if (tid < TMTOK) {
        int tk = g_perm[p0 + tid];
        s_tok[tid] = tk;
        s_w[tid] = (tk >= 0) ? g_pw[p0 + tid] : 0.f;
    }
    __syncthreads();

    const uint32_t bufs[2] = { sb, sb + STAGE };
    const int rbase = wm * 32 + (lane >> 2);

    ld_g1(bufs[0], s_tok, e, nc, 0); CP_COMMIT();
    float c1[2][4][4], c3[2][4][4];
#pragma unroll
    for (int a = 0; a < 2; a++)
#pragma unroll
        for (int b = 0; b < 4; b++)
#pragma unroll
            for (int c = 0; c < 4; c++) { c1[a][b][c] = 0.f; c3[a][b][c] = 0.f; }

    for (int k = 0; k < 32; k++) {
        CP_WAIT(0);
        __syncthreads();
        if (k + 1 < 32) { ld_g1(bufs[(k + 1) & 1], s_tok, e, nc, k + 1); CP_COMMIT(); }
        uint32_t cb = bufs[k & 1];
#pragma unroll
        for (int ks = 0; ks < 2; ks++) {
            uint32_t ah[2][4], al[2][4];
            ldm4(ah[0], adr(cb, wm * 32,            ks, lane));
            ldm4(ah[1], adr(cb, wm * 32 + 16,       ks, lane));
            ldm4(al[0], adr(cb, 128 + wm * 32,      ks, lane));
            ldm4(al[1], adr(cb, 128 + wm * 32 + 16, ks, lane));
            uint32_t b1h[2][4], b1l[2][4], b3h[2][4], b3l[2][4];
            ldm4(b1h[0], adr(cb, 256 + wn * 32,      ks, lane));
            ldm4(b1h[1], adr(cb, 256 + wn * 32 + 16, ks, lane));
            ldm4(b1l[0], adr(cb, 320 + wn * 32,      ks, lane));
            ldm4(b1l[1], adr(cb, 320 + wn * 32 + 16, ks, lane));
            ldm4(b3h[0], adr(cb, 384 + wn * 32,      ks, lane));
            ldm4(b3h[1], adr(cb, 384 + wn * 32 + 16, ks, lane));
            ldm4(b3l[0], adr(cb, 448 + wn * 32,      ks, lane));
            ldm4(b3l[1], adr(cb, 448 + wn * 32 + 16, ks, lane));
            // term-major: independent MMA groups
#pragma unroll
            for (int nj = 0; nj < 2; nj++)
#pragma unroll
                for (int nk = 0; nk < 2; nk++)
#pragma unroll
                    for (int mi = 0; mi < 2; mi++) mma16(c1[mi][nj*2+nk], ah[mi], b1h[nj][nk], b1h[nj][nk+2]);
#pragma unroll
            for (int nj = 0; nj < 2; nj++)
#pragma unroll
                for (int nk = 0; nk < 2; nk++)
#pragma unroll
                    for (int mi = 0; mi < 2; mi++) mma16(c3[mi][nj*2+nk], ah[mi], b3h[nj][nk], b3h[nj][nk+2]);
#pragma unroll
            for (int nj = 0; nj < 2; nj++)
#pragma unroll
                for (int nk = 0; nk < 2; nk++)
#pragma unroll
                    for (int mi = 0; mi < 2; mi++) mma16(c1[mi][nj*2+nk], al[mi], b1h[nj][nk], b1h[nj][nk+2]);
#pragma unroll
            for (int nj = 0; nj < 2; nj++)
#pragma unroll
                for (int nk = 0; nk < 2; nk++)
#pragma unroll
                    for (int mi = 0; mi < 2; mi++) mma16(c3[mi][nj*2+nk], al[mi], b3h[nj][nk], b3h[nj][nk+2]);
#pragma unroll
            for (int nj = 0; nj < 2; nj++)
#pragma unroll
                for (int nk = 0; nk < 2; nk++)
#pragma unroll
                    for (int mi = 0; mi < 2; mi++) mma16(c1[mi][nj*2+nk], ah[mi], b1l[nj][nk], b1l[nj][nk+2]);
#pragma unroll
            for (int nj = 0; nj < 2; nj++)
#pragma unroll
                for (int nk = 0; nk < 2; nk++)
#pragma unroll
                    for (int mi = 0; mi < 2; mi++) mma16(c3[mi][nj*2+nk], ah[mi], b3l[nj][nk], b3l[nj][nk+2]);
        }
    }
    // epilogue: silu(h1)*h3*w -> bf16 hi/lo a-scratch
#pragma unroll
    for (int mi = 0; mi < 2; mi++)
#pragma unroll
        for (int n4 = 0; n4 < 4; n4++)
#pragma unroll
            for (int hf = 0; hf < 2; hf++) {
                int row = rbase + mi * 16 + hf * 8;
                int col = nc * 64 + wn * 32 + n4 * 8 + ((lane & 3) << 1);
                float w = s_w[row];
                float h1a = c1[mi][n4][hf * 2], h1b = c1[mi][n4][hf * 2 + 1];
                float a0 = h1a / (1.f + __expf(-h1a)) * c3[mi][n4][hf * 2] * w;
                float a1 = h1b / (1.f + __expf(-h1b)) * c3[mi][n4][hf * 2 + 1] * w;
                uint32_t hv, lv; split2(a0, a1, hv, lv);
                size_t o = ((size_t)(tile * TMTOK + row) * IDIM + col) >> 1;
                g_ahi32[o] = hv; g_alo32[o] = lv;
            }
}

// ---- GEMM2: y for H-chunk of 128. grid (NTILES, 8) ----
__global__ void __launch_bounds__(256, 2) k_g2() {
    const int tile = blockIdx.x;
    if (tile >= g_tile_off[E]) return;
    const int nc = blockIdx.y;
    extern __shared__ char sm[];
    const uint32_t sb = smem_u32(sm);

    const int tid = threadIdx.x, lane = tid & 31, wid = tid >> 5;
    const int wm = wid & 3, wn = wid >> 2;   // 4(M) x 2(N): warp M32 x N64

    const int e = g_texp[tile];
    const uint32_t bufs[2] = { sb, sb + STAGE };
    const int rbase = wm * 32 + (lane >> 2);

    ld_g2(bufs[0], tile, e, nc, 0); CP_COMMIT();
    float cc[2][8][4];
#pragma unroll
    for (int a = 0; a < 2; a++)
#pragma unroll
        for (int b = 0; b < 8; b++)
#pragma unroll
            for (int c = 0; c < 4; c++) cc[a][b][c] = 0.f;

    for (int k = 0; k < 16; k++) {
        CP_WAIT(0);
        __syncthreads();
        if (k + 1 < 16) { ld_g2(bufs[(k + 1) & 1], tile, e, nc, k + 1); CP_COMMIT(); }
        uint32_t cb = bufs[k & 1];
#pragma unroll
        for (int ks = 0; ks < 2; ks++) {
            uint32_t ah[2][4], al[2][4];
            ldm4(ah[0], adr(cb, wm * 32,            ks, lane));
            ldm4(ah[1], adr(cb, wm * 32 + 16,       ks, lane));
            ldm4(al[0], adr(cb, 128 + wm * 32,      ks, lane));
            ldm4(al[1], adr(cb, 128 + wm * 32 + 16, ks, lane));
            uint32_t b2h[4][4], b2l[4][4];
#pragma unroll
            for (int nj = 0; nj < 4; nj++) {
                ldm4(b2h[nj], adr(cb, 256 + wn * 64 + nj * 16, ks, lane));
                ldm4(b2l[nj], adr(cb, 384 + wn * 64 + nj * 16, ks, lane));
            }
#pragma unroll
            for (int nj = 0; nj < 4; nj++)
#pragma unroll
                for (int nk = 0; nk < 2; nk++)
#pragma unroll
                    for (int mi = 0; mi < 2; mi++) mma16(cc[mi][nj*2+nk], ah[mi], b2h[nj][nk], b2h[nj][nk+2]);
#pragma unroll
            for (int nj = 0; nj < 4; nj++)
#pragma unroll
                for (int nk = 0; nk < 2; nk++)
#pragma unroll
                    for (int mi = 0; mi < 2; mi++) mma16(cc[mi][nj*2+nk], al[mi], b2h[nj][nk], b2h[nj][nk+2]);
#pragma unroll
            for (int nj = 0; nj < 4; nj++)
#pragma unroll
                for (int nk = 0; nk < 2; nk++)
#pragma unroll
                    for (int mi = 0; mi < 2; mi++) mma16(cc[mi][nj*2+nk], ah[mi], b2l[nj][nk], b2l[nj][nk+2]);
        }
    }
#pragma unroll
    for (int mi = 0; mi < 2; mi++)
#pragma unroll
        for (int n8 = 0; n8 < 8; n8++)
#pragma unroll
            for (int hf = 0; hf < 2; hf++) {
                int row = rbase + mi * 16 + hf * 8;
                int col = nc * 128 + wn * 64 + n8 * 8 + ((lane & 3) << 1);
                float2 v = make_float2(cc[mi][n8][hf * 2], cc[mi][n8][hf * 2 + 1]);
                *(float2*)&g_y[(size_t)(tile * TMTOK + row) * H + col] = v;
            }
}

// ---------------- gather ----------------
__global__ void k_gather(float* __restrict__ out) {
    int idx = blockIdx.x * 256 + threadIdx.x;
    if (idx >= T * H / 4) return;
    int t = idx / (H / 4), c = idx % (H / 4);
    int p0 = g_ypos[2 * t], p1 = g_ypos[2 * t + 1];
    float4 a = ((const float4*)g_y)[(size_t)p0 * (H / 4) + c];
    float4 b = ((const float4*)g_y)[(size_t)p1 * (H / 4) + c];
    ((float4*)out)[idx] = make_float4(a.x + b.x, a.y + b.y, a.z + b.z, a.w + b.w);
}

// ---------------- launch ----------------
extern "C" void kernel_launch(void* const* d_in, const int* in_sizes, int n_in,
                              void* d_out, int out_size) {
    const float* x  = (const float*)d_in[0];
    const float* gw = (const float*)d_in[1];
    const float* gb = (const float*)d_in[2];
    const float* W1 = (const float*)d_in[3];
    const float* W2 = (const float*)d_in[4];
    const float* W3 = (const float*)d_in[5];
    float* out = (float*)d_out;

    cudaFuncSetAttribute(k_router, cudaFuncAttributeMaxDynamicSharedMemorySize, 86016);
    cudaFuncSetAttribute(k_g1,     cudaFuncAttributeMaxDynamicSharedMemorySize, SMEM_REQ);
    cudaFuncSetAttribute(k_g2,     cudaFuncAttributeMaxDynamicSharedMemorySize, SMEM_REQ);

    k_cvt<<<2048, 256>>>(x, W1, W2, W3);
    k_router<<<T / 16, 256, 86016>>>(x, gw, gb);
    k_aux<<<1, 256>>>();
    k_g1<<<dim3(NTILES, 8), 256, SMEM_REQ>>>();
    k_g2<<<dim3(NTILES, 8), 256, SMEM_REQ>>>();
    k_gather<<<(T * H / 4 + 255) / 256, 256>>>(out);
}

// round 9
// speedup vs baseline: 1.6369x; 1.1046x over previous
#include <cuda_runtime.h>
#include <cuda_fp16.h>
#include <math.h>
#include <stdint.h>

#define T      4096
#define H      1024
#define IDIM   512
#define E      64
#define TOPK   2
#define TMTOK  128
#define NTILES 128
#define PPOS   (T*TOPK + E*TMTOK)

// ---------------- device scratch ----------------
__device__ int   g_off[E+1];
__device__ int   g_tile_off[E+1];
__device__ int   g_texp[NTILES];
__device__ int   g_perm[PPOS];
__device__ float g_pw[PPOS];
__device__ int   g_sel[T*TOPK];
__device__ float g_w[T*TOPK];
__device__ int   g_ypos[T*TOPK];
// fp16 scratch: x split hi/lo, weights single fp16
__device__ uint2 g_xh[(T+1)*H/4], g_xl[(T+1)*H/4];
__device__ uint2 g_w1h[E*IDIM*H/4];
__device__ uint2 g_w3h[E*IDIM*H/4];
__device__ uint2 g_w2h[E*H*IDIM/4];
__device__ uint32_t g_ah32[NTILES*TMTOK*IDIM/2], g_al32[NTILES*TMTOK*IDIM/2];
__device__ float g_y[(size_t)NTILES*TMTOK*H];

// ---------------- helpers ----------------
__device__ __forceinline__ uint32_t smem_u32(const void* p) {
    uint32_t a;
    asm("{ .reg .u64 t; cvta.to.shared.u64 t, %1; cvt.u32.u64 %0, t; }" : "=r"(a) : "l"(p));
    return a;
}
__device__ __forceinline__ void cpa16(uint32_t dst, const void* src) {
    asm volatile("cp.async.cg.shared.global [%0], [%1], 16;" :: "r"(dst), "l"(src) : "memory");
}
#define CP_COMMIT() asm volatile("cp.async.commit_group;" ::: "memory")
#define CP_WAIT(n)  asm volatile("cp.async.wait_group %0;" :: "n"(n) : "memory")

__device__ __forceinline__ void ldm4(uint32_t* r, uint32_t addr) {
    asm volatile("ldmatrix.sync.aligned.m8n8.x4.shared.b16 {%0,%1,%2,%3}, [%4];"
        : "=r"(r[0]), "=r"(r[1]), "=r"(r[2]), "=r"(r[3]) : "r"(addr));
}
__device__ __forceinline__ void mma16(float* d, const uint32_t* a, uint32_t b0, uint32_t b1) {
    asm volatile("mma.sync.aligned.m16n8k16.row.col.f32.f16.f16.f32 "
        "{%0,%1,%2,%3}, {%4,%5,%6,%7}, {%8,%9}, {%0,%1,%2,%3};"
        : "+f"(d[0]), "+f"(d[1]), "+f"(d[2]), "+f"(d[3])
        : "r"(a[0]), "r"(a[1]), "r"(a[2]), "r"(a[3]), "r"(b0), "r"(b1));
}
// pack two floats -> fp16x2 (lo=a, hi=b)
__device__ __forceinline__ uint32_t f16x2(float a, float b) {
    uint32_t r;
    asm("cvt.rn.f16x2.f32 %0, %1, %2;" : "=r"(r) : "f"(b), "f"(a));
    return r;
}
// fp32 pair -> fp16 hi + fp16 lo residual
__device__ __forceinline__ void split2h(float a, float b, uint32_t& hi, uint32_t& lo) {
    hi = f16x2(a, b);
    __half2 hh = *reinterpret_cast<__half2*>(&hi);
    float2 hf = __half22float2(hh);
    lo = f16x2(a - hf.x, b - hf.y);
}

// ---------------- convert fp32 -> fp16 scratch ----------------
#define X4   (T*H/4)
#define W14  (E*IDIM*H/4)
#define TOT4 (X4 + 3*W14)
__global__ void k_cvt(const float* __restrict__ x, const float* __restrict__ W1,
                      const float* __restrict__ W2, const float* __restrict__ W3) {
    size_t gid = (size_t)blockIdx.x * blockDim.x + threadIdx.x;
    size_t stride = (size_t)gridDim.x * blockDim.x;
    if (gid < H/4) { g_xh[(size_t)T*H/4 + gid] = make_uint2(0,0); g_xl[(size_t)T*H/4 + gid] = make_uint2(0,0); }
    for (size_t i = gid; i < TOT4; i += stride) {
        size_t j = i;
        if (j < X4) {
            float4 v = ((const float4*)x)[j];
            uint32_t h0, l0, h1, l1;
            split2h(v.x, v.y, h0, l0);
            split2h(v.z, v.w, h1, l1);
            g_xh[j] = make_uint2(h0, h1);
            g_xl[j] = make_uint2(l0, l1);
        } else {
            j -= X4;
            const float4* s; uint2* dh;
            if (j < W14)       { s = (const float4*)W1; dh = g_w1h; }
            else { j -= W14;
                if (j < W14)   { s = (const float4*)W3; dh = g_w3h; }
                else { j -= W14; s = (const float4*)W2; dh = g_w2h; } }
            float4 v = s[j];
            dh[j] = make_uint2(f16x2(v.x, v.y), f16x2(v.z, v.w));
        }
    }
}

// ---------------- router (16 tokens / block) ----------------
__global__ void __launch_bounds__(256) k_router(const float* __restrict__ x,
                                                const float* __restrict__ gw,
                                                const float* __restrict__ gb) {
    extern __shared__ float rsm[];
    float* xs  = rsm;
    float* red = rsm + 16384;
    float* lg  = red + 4096;
    const int t0 = blockIdx.x * 16;
    const int tid = threadIdx.x;
    float4* xs4 = (float4*)xs;
    const float4* xg = (const float4*)(x + (size_t)t0 * H);
    for (int i = tid; i < 16 * H / 4; i += 256) xs4[i] = xg[i];
    __syncthreads();
    const int e = tid & 63, ck = tid >> 6;
    const float4* gwp = (const float4*)(gw + (size_t)e * H + ck * 256);
    float acc[16];
#pragma unroll
    for (int r = 0; r < 16; r++) acc[r] = 0.f;
    for (int j = 0; j < 64; j++) {
        float4 wv = gwp[j];
#pragma unroll
        for (int r = 0; r < 16; r++) {
            float4 xv = xs4[r * 256 + ck * 64 + j];
            acc[r] += xv.x * wv.x + xv.y * wv.y + xv.z * wv.z + xv.w * wv.w;
        }
    }
#pragma unroll
    for (int r = 0; r < 16; r++) red[tid * 16 + r] = acc[r];
    __syncthreads();
    if (tid < 64) {
#pragma unroll
        for (int r = 0; r < 16; r++)
            lg[r * 64 + tid] = red[tid * 16 + r] + red[(tid + 64) * 16 + r] +
                               red[(tid + 128) * 16 + r] + red[(tid + 192) * 16 + r] + gb[tid];
    }
    __syncthreads();
    if (tid < 16) {
        int t = t0 + tid;
        float l0 = -1e30f, l1 = -1e30f;
        int e0 = 0, e1 = 0;
        for (int k = 0; k < E; k++) {
            float l = lg[tid * 64 + k];
            if (l > l0)      { l1 = l0; e1 = e0; l0 = l; e0 = k; }
            else if (l > l1) { l1 = l;  e1 = k; }
        }
        float rr = expf(l1 - l0);
        float w0 = 1.f / (1.f + rr);
        float w1 = rr * w0;
        g_sel[2 * t] = e0;  g_sel[2 * t + 1] = e1;
        g_w[2 * t]   = w0;  g_w[2 * t + 1]   = w1;
    }
}

// ---------------- aux: histogram + scan + pad + scatter ----------------
__global__ void __launch_bounds__(256) k_aux() {
    __shared__ int hist[E];
    __shared__ int soff[E+1], stoff[E+1];
    __shared__ int cur[E];
    const int tid = threadIdx.x;
    if (tid < E) hist[tid] = 0;
    __syncthreads();
    for (int i = tid; i < T * TOPK; i += 256) atomicAdd(&hist[g_sel[i]], 1);
    __syncthreads();
    if (tid == 0) {
        int off = 0, toff = 0;
        for (int e = 0; e < E; e++) {
            soff[e] = off; stoff[e] = toff;
            int tiles = (hist[e] + TMTOK - 1) / TMTOK;
            for (int q = 0; q < tiles; q++) g_texp[toff + q] = e;
            off += tiles * TMTOK; toff += tiles;
        }
        soff[E] = off; stoff[E] = toff;
    }
    __syncthreads();
    if (tid < E) { cur[tid] = soff[tid]; g_off[tid] = soff[tid]; g_tile_off[tid] = stoff[tid]; }
    if (tid == 0) { g_off[E] = soff[E]; g_tile_off[E] = stoff[E]; }
    for (int i = tid; i < PPOS; i += 256) g_perm[i] = -1;
    __syncthreads();
    for (int i = tid; i < T * TOPK; i += 256) {
        int e = g_sel[i];
        int pos = atomicAdd(&cur[e], 1);
        g_perm[pos] = i >> 1;
        g_pw[pos] = g_w[i];
        int local = pos - soff[e];
        g_ypos[i] = (stoff[e] + (local >> 7)) * TMTOK + (local & 127);
    }
}

// ---------------- FFN GEMMs: 2D grid (tile, n-chunk), fp16 2-term ----------------
#define KC      32
#define RSTRIDE 80
#define STAGE   (384*RSTRIDE)     // 30720 B
#define SMEM_REQ (2*STAGE)        // 61440 B

__device__ __forceinline__ uint32_t adr(uint32_t buf, int rowbase, int ks, int lane) {
    return buf + (uint32_t)(rowbase + (lane & 15)) * RSTRIDE + (uint32_t)(ks * 2 + (lane >> 4)) * 16;
}

// g1 stage rows (64B): [0,128)xh [128,256)xl [256,320)w1 [320,384)w3
__device__ __forceinline__ void ld1row(uint32_t buf, const int* s_tok, int e, int nc, int k, int row) {
    const char* src;
    if (row < 256) {
        int tok = s_tok[row & 127];
        if (tok < 0) tok = T;
        const char* base = (row < 128) ? (const char*)g_xh : (const char*)g_xl;
        src = base + (size_t)tok * (H * 2) + k * (KC * 2);
    } else {
        int n = row & 63;
        const char* base = (row < 320) ? (const char*)g_w1h : (const char*)g_w3h;
        src = base + ((size_t)(e * IDIM + nc * 64 + n)) * (H * 2) + k * (KC * 2);
    }
    uint32_t d = buf + (uint32_t)row * RSTRIDE;
#pragma unroll
    for (int q = 0; q < 4; q++) cpa16(d + q * 16, src + q * 16);
}
__device__ __forceinline__ void ld_g1(uint32_t buf, const int* s_tok, int e, int nc, int k) {
    ld1row(buf, s_tok, e, nc, k, threadIdx.x);
    if (threadIdx.x < 128) ld1row(buf, s_tok, e, nc, k, 256 + threadIdx.x);
}
// g2 stage rows: [0,128)ah [128,256)al [256,384)w2
__device__ __forceinline__ void ld2row(uint32_t buf, int tile, int e, int nc, int k, int row) {
    const char* src;
    if (row < 256) {
        const char* base = (row < 128) ? (const char*)g_ah32 : (const char*)g_al32;
        src = base + ((size_t)tile * TMTOK + (row & 127)) * (IDIM * 2) + k * (KC * 2);
    } else {
        int n = row & 127;
        src = (const char*)g_w2h + ((size_t)(e * H + nc * 128 + n)) * (IDIM * 2) + k * (KC * 2);
    }
    uint32_t d = buf + (uint32_t)row * RSTRIDE;
#pragma unroll
    for (int q = 0; q < 4; q++) cpa16(d + q * 16, src + q * 16);
}
__device__ __forceinline__ void ld_g2(uint32_t buf, int tile, int e, int nc, int k) {
    ld2row(buf, tile, e, nc, k, threadIdx.x);
    if (threadIdx.x < 128) ld2row(buf, tile, e, nc, k, 256 + threadIdx.x);
}

// ---- GEMM1: h1/h3 for I-chunk of 64, silu epilogue. grid (NTILES, 8) ----
__global__ void __launch_bounds__(256, 2) k_g1() {
    const int tile = blockIdx.x;
    if (tile >= g_tile_off[E]) return;
    const int nc = blockIdx.y;
    extern __shared__ char sm[];
    const uint32_t sb = smem_u32(sm);
    __shared__ int   s_tok[TMTOK];
    __shared__ float s_w[TMTOK];

    const int tid = threadIdx.x, lane = tid & 31, wid = tid >> 5;
    const int wm = wid & 3, wn = wid >> 2;   // 4(M) x 2(N): warp M32 x N32

    const int e = g_texp[tile];
    const int p0 = g_off[e] + (tile - g_tile_off[e]) * TMTOK;

    if (tid < TMTOK) {
        int tk = g_perm[p0 + tid];
        s_tok[tid] = tk;
        s_w[tid] = (tk >= 0) ? g_pw[p0 + tid] : 0.f;
    }
    __syncthreads();

    const uint32_t bufs[2] = { sb, sb + STAGE };
    const int rbase = wm * 32 + (lane >> 2);

    ld_g1(bufs[0], s_tok, e, nc, 0); CP_COMMIT();
    float c1[2][4][4], c3[2][4][4];
#pragma unroll
    for (int a = 0; a < 2; a++)
#pragma unroll
        for (int b = 0; b < 4; b++)
#pragma unroll
            for (int c = 0; c < 4; c++) { c1[a][b][c] = 0.f; c3[a][b][c] = 0.f; }

    for (int k = 0; k < 32; k++) {
        CP_WAIT(0);
        __syncthreads();
        if (k + 1 < 32) { ld_g1(bufs[(k + 1) & 1], s_tok, e, nc, k + 1); CP_COMMIT(); }
        uint32_t cb = bufs[k & 1];
#pragma unroll
        for (int ks = 0; ks < 2; ks++) {
            uint32_t ah[2][4], al[2][4];
            ldm4(ah[0], adr(cb, wm * 32,            ks, lane));
            ldm4(ah[1], adr(cb, wm * 32 + 16,       ks, lane));
            ldm4(al[0], adr(cb, 128 + wm * 32,      ks, lane));
            ldm4(al[1], adr(cb, 128 + wm * 32 + 16, ks, lane));
            uint32_t b1[2][4], b3[2][4];
            ldm4(b1[0], adr(cb, 256 + wn * 32,      ks, lane));
            ldm4(b1[1], adr(cb, 256 + wn * 32 + 16, ks, lane));
            ldm4(b3[0], adr(cb, 320 + wn * 32,      ks, lane));
            ldm4(b3[1], adr(cb, 320 + wn * 32 + 16, ks, lane));
            // term-major fp16 2-term
#pragma unroll
            for (int nj = 0; nj < 2; nj++)
#pragma unroll
                for (int nk = 0; nk < 2; nk++)
#pragma unroll
                    for (int mi = 0; mi < 2; mi++) mma16(c1[mi][nj*2+nk], ah[mi], b1[nj][nk], b1[nj][nk+2]);
#pragma unroll
            for (int nj = 0; nj < 2; nj++)
#pragma unroll
                for (int nk = 0; nk < 2; nk++)
#pragma unroll
                    for (int mi = 0; mi < 2; mi++) mma16(c3[mi][nj*2+nk], ah[mi], b3[nj][nk], b3[nj][nk+2]);
#pragma unroll
            for (int nj = 0; nj < 2; nj++)
#pragma unroll
                for (int nk = 0; nk < 2; nk++)
#pragma unroll
                    for (int mi = 0; mi < 2; mi++) mma16(c1[mi][nj*2+nk], al[mi], b1[nj][nk], b1[nj][nk+2]);
#pragma unroll
            for (int nj = 0; nj < 2; nj++)
#pragma unroll
                for (int nk = 0; nk < 2; nk++)
#pragma unroll
                    for (int mi = 0; mi < 2; mi++) mma16(c3[mi][nj*2+nk], al[mi], b3[nj][nk], b3[nj][nk+2]);
        }
    }
    // epilogue: silu(h1)*h3*w -> fp16 hi/lo a-scratch
#pragma unroll
    for (int mi = 0; mi < 2; mi++)
#pragma unroll
        for (int n4 = 0; n4 < 4; n4++)
#pragma unroll
            for (int hf = 0; hf < 2; hf++) {
                int row = rbase + mi * 16 + hf * 8;
                int col = nc * 64 + wn * 32 + n4 * 8 + ((lane & 3) << 1);
                float w = s_w[row];
                float h1a = c1[mi][n4][hf * 2], h1b = c1[mi][n4][hf * 2 + 1];
                float a0 = h1a / (1.f + __expf(-h1a)) * c3[mi][n4][hf * 2] * w;
                float a1 = h1b / (1.f + __expf(-h1b)) * c3[mi][n4][hf * 2 + 1] * w;
                uint32_t hv, lv; split2h(a0, a1, hv, lv);
                size_t o = ((size_t)(tile * TMTOK + row) * IDIM + col) >> 1;
                g_ah32[o] = hv; g_al32[o] = lv;
            }
}

// ---- GEMM2: y for H-chunk of 128. grid (NTILES, 8) ----
__global__ void __launch_bounds__(256, 2) k_g2() {
    const int tile = blockIdx.x;
    if (tile >= g_tile_off[E]) return;
    const int nc = blockIdx.y;
    extern __shared__ char sm[];
    const uint32_t sb = smem_u32(sm);

    const int tid = threadIdx.x, lane = tid & 31, wid = tid >> 5;
    const int wm = wid & 3, wn = wid >> 2;   // 4(M) x 2(N): warp M32 x N64

    const int e = g_texp[tile];
    const uint32_t bufs[2] = { sb, sb + STAGE };
    const int rbase = wm * 32 + (lane >> 2);

    ld_g2(bufs[0], tile, e, nc, 0); CP_COMMIT();
    float cc[2][8][4];
#pragma unroll
    for (int a = 0; a < 2; a++)
#pragma unroll
        for (int b = 0; b < 8; b++)
#pragma unroll
            for (int c = 0; c < 4; c++) cc[a][b][c] = 0.f;

    for (int k = 0; k < 16; k++) {
        CP_WAIT(0);
        __syncthreads();
        if (k + 1 < 16) { ld_g2(bufs[(k + 1) & 1], tile, e, nc, k + 1); CP_COMMIT(); }
        uint32_t cb = bufs[k & 1];
#pragma unroll
        for (int ks = 0; ks < 2; ks++) {
            uint32_t ah[2][4], al[2][4];
            ldm4(ah[0], adr(cb, wm * 32,            ks, lane));
            ldm4(ah[1], adr(cb, wm * 32 + 16,       ks, lane));
            ldm4(al[0], adr(cb, 128 + wm * 32,      ks, lane));
            ldm4(al[1], adr(cb, 128 + wm * 32 + 16, ks, lane));
            uint32_t b2[4][4];
#pragma unroll
            for (int nj = 0; nj < 4; nj++)
                ldm4(b2[nj], adr(cb, 256 + wn * 64 + nj * 16, ks, lane));
#pragma unroll
            for (int nj = 0; nj < 4; nj++)
#pragma unroll
                for (int nk = 0; nk < 2; nk++)
#pragma unroll
                    for (int mi = 0; mi < 2; mi++) mma16(cc[mi][nj*2+nk], ah[mi], b2[nj][nk], b2[nj][nk+2]);
#pragma unroll
            for (int nj = 0; nj < 4; nj++)
#pragma unroll
                for (int nk = 0; nk < 2; nk++)
#pragma unroll
                    for (int mi = 0; mi < 2; mi++) mma16(cc[mi][nj*2+nk], al[mi], b2[nj][nk], b2[nj][nk+2]);
        }
    }
#pragma unroll
    for (int mi = 0; mi < 2; mi++)
#pragma unroll
        for (int n8 = 0; n8 < 8; n8++)
#pragma unroll
            for (int hf = 0; hf < 2; hf++) {
                int row = rbase + mi * 16 + hf * 8;
                int col = nc * 128 + wn * 64 + n8 * 8 + ((lane & 3) << 1);
                float2 v = make_float2(cc[mi][n8][hf * 2], cc[mi][n8][hf * 2 + 1]);
                *(float2*)&g_y[(size_t)(tile * TMTOK + row) * H + col] = v;
            }
}

// ---------------- gather ----------------
__global__ void k_gather(float* __restrict__ out) {
    int idx = blockIdx.x * 256 + threadIdx.x;
    if (idx >= T * H / 4) return;
    int t = idx / (H / 4), c = idx % (H / 4);
    int p0 = g_ypos[2 * t], p1 = g_ypos[2 * t + 1];
    float4 a = ((const float4*)g_y)[(size_t)p0 * (H / 4) + c];
    float4 b = ((const float4*)g_y)[(size_t)p1 * (H / 4) + c];
    ((float4*)out)[idx] = make_float4(a.x + b.x, a.y + b.y, a.z + b.z, a.w + b.w);
}

// ---------------- launch ----------------
extern "C" void kernel_launch(void* const* d_in, const int* in_sizes, int n_in,
                              void* d_out, int out_size) {
    const float* x  = (const float*)d_in[0];
    const float* gw = (const float*)d_in[1];
    const float* gb = (const float*)d_in[2];
    const float* W1 = (const float*)d_in[3];
    const float* W2 = (const float*)d_in[4];
    const float* W3 = (const float*)d_in[5];
    float* out = (float*)d_out;

    cudaFuncSetAttribute(k_router, cudaFuncAttributeMaxDynamicSharedMemorySize, 86016);
    cudaFuncSetAttribute(k_g1,     cudaFuncAttributeMaxDynamicSharedMemorySize, SMEM_REQ);
    cudaFuncSetAttribute(k_g2,     cudaFuncAttributeMaxDynamicSharedMemorySize, SMEM_REQ);

    k_cvt<<<2048, 256>>>(x, W1, W2, W3);
    k_router<<<T / 16, 256, 86016>>>(x, gw, gb);
    k_aux<<<1, 256>>>();
    k_g1<<<dim3(NTILES, 8), 256, SMEM_REQ>>>();
    k_g2<<<dim3(NTILES, 8), 256, SMEM_REQ>>>();
    k_gather<<<(T * H / 4 + 255) / 256, 256>>>(out);
}

// round 10
// speedup vs baseline: 2.2832x; 1.3948x over previous
#include <cuda_runtime.h>
#include <cuda_fp16.h>
#include <math.h>
#include <stdint.h>

#define T      4096
#define H      1024
#define IDIM   512
#define E      64
#define TOPK   2
#define TMTOK  64
#define NTILES 192
#define PPOS   (T*TOPK + E*TMTOK)

// ---------------- device scratch ----------------
__device__ int   g_off[E+1];
__device__ int   g_tile_off[E+1];
__device__ int   g_texp[NTILES];
__device__ int   g_perm[PPOS];
__device__ float g_pw[PPOS];
__device__ int   g_sel[T*TOPK];
__device__ float g_w[T*TOPK];
__device__ int   g_ypos[T*TOPK];
// fp16 scratch: x split hi/lo, weights single fp16
__device__ uint2 g_xh[(T+1)*H/4], g_xl[(T+1)*H/4];
__device__ uint2 g_w1h[E*IDIM*H/4];
__device__ uint2 g_w3h[E*IDIM*H/4];
__device__ uint2 g_w2h[E*H*IDIM/4];
__device__ uint32_t g_ah32[NTILES*TMTOK*IDIM/2], g_al32[NTILES*TMTOK*IDIM/2];
__device__ float g_y[(size_t)NTILES*TMTOK*H];

// ---------------- helpers ----------------
__device__ __forceinline__ uint32_t smem_u32(const void* p) {
    uint32_t a;
    asm("{ .reg .u64 t; cvta.to.shared.u64 t, %1; cvt.u32.u64 %0, t; }" : "=r"(a) : "l"(p));
    return a;
}
__device__ __forceinline__ void cpa16(uint32_t dst, const void* src) {
    asm volatile("cp.async.cg.shared.global [%0], [%1], 16;" :: "r"(dst), "l"(src) : "memory");
}
#define CP_COMMIT() asm volatile("cp.async.commit_group;" ::: "memory")
#define CP_WAIT(n)  asm volatile("cp.async.wait_group %0;" :: "n"(n) : "memory")

__device__ __forceinline__ void ldm4(uint32_t* r, uint32_t addr) {
    asm volatile("ldmatrix.sync.aligned.m8n8.x4.shared.b16 {%0,%1,%2,%3}, [%4];"
        : "=r"(r[0]), "=r"(r[1]), "=r"(r[2]), "=r"(r[3]) : "r"(addr));
}
__device__ __forceinline__ void mma16(float* d, const uint32_t* a, uint32_t b0, uint32_t b1) {
    asm volatile("mma.sync.aligned.m16n8k16.row.col.f32.f16.f16.f32 "
        "{%0,%1,%2,%3}, {%4,%5,%6,%7}, {%8,%9}, {%0,%1,%2,%3};"
        : "+f"(d[0]), "+f"(d[1]), "+f"(d[2]), "+f"(d[3])
        : "r"(a[0]), "r"(a[1]), "r"(a[2]), "r"(a[3]), "r"(b0), "r"(b1));
}
__device__ __forceinline__ uint32_t f16x2(float a, float b) {
    uint32_t r;
    asm("cvt.rn.f16x2.f32 %0, %1, %2;" : "=r"(r) : "f"(b), "f"(a));
    return r;
}
__device__ __forceinline__ void split2h(float a, float b, uint32_t& hi, uint32_t& lo) {
    hi = f16x2(a, b);
    __half2 hh = *reinterpret_cast<__half2*>(&hi);
    float2 hf = __half22float2(hh);
    lo = f16x2(a - hf.x, b - hf.y);
}

// ---------------- convert fp32 -> fp16 scratch ----------------
#define X4   (T*H/4)
#define W14  (E*IDIM*H/4)
#define TOT4 (X4 + 3*W14)
__global__ void k_cvt(const float* __restrict__ x, const float* __restrict__ W1,
                      const float* __restrict__ W2, const float* __restrict__ W3) {
    size_t gid = (size_t)blockIdx.x * blockDim.x + threadIdx.x;
    size_t stride = (size_t)gridDim.x * blockDim.x;
    if (gid < H/4) { g_xh[(size_t)T*H/4 + gid] = make_uint2(0,0); g_xl[(size_t)T*H/4 + gid] = make_uint2(0,0); }
    for (size_t i = gid; i < TOT4; i += stride) {
        size_t j = i;
        if (j < X4) {
            float4 v = ((const float4*)x)[j];
            uint32_t h0, l0, h1, l1;
            split2h(v.x, v.y, h0, l0);
            split2h(v.z, v.w, h1, l1);
            g_xh[j] = make_uint2(h0, h1);
            g_xl[j] = make_uint2(l0, l1);
        } else {
            j -= X4;
            const float4* s; uint2* dh;
            if (j < W14)       { s = (const float4*)W1; dh = g_w1h; }
            else { j -= W14;
                if (j < W14)   { s = (const float4*)W3; dh = g_w3h; }
                else { j -= W14; s = (const float4*)W2; dh = g_w2h; } }
            float4 v = s[j];
            dh[j] = make_uint2(f16x2(v.x, v.y), f16x2(v.z, v.w));
        }
    }
}

// ---------------- router (16 tokens / block) ----------------
__global__ void __launch_bounds__(256) k_router(const float* __restrict__ x,
                                                const float* __restrict__ gw,
                                                const float* __restrict__ gb) {
    extern __shared__ float rsm[];
    float* xs  = rsm;
    float* red = rsm + 16384;
    float* lg  = red + 4096;
    const int t0 = blockIdx.x * 16;
    const int tid = threadIdx.x;
    float4* xs4 = (float4*)xs;
    const float4* xg = (const float4*)(x + (size_t)t0 * H);
    for (int i = tid; i < 16 * H / 4; i += 256) xs4[i] = xg[i];
    __syncthreads();
    const int e = tid & 63, ck = tid >> 6;
    const float4* gwp = (const float4*)(gw + (size_t)e * H + ck * 256);
    float acc[16];
#pragma unroll
    for (int r = 0; r < 16; r++) acc[r] = 0.f;
    for (int j = 0; j < 64; j++) {
        float4 wv = gwp[j];
#pragma unroll
        for (int r = 0; r < 16; r++) {
            float4 xv = xs4[r * 256 + ck * 64 + j];
            acc[r] += xv.x * wv.x + xv.y * wv.y + xv.z * wv.z + xv.w * wv.w;
        }
    }
#pragma unroll
    for (int r = 0; r < 16; r++) red[tid * 16 + r] = acc[r];
    __syncthreads();
    if (tid < 64) {
#pragma unroll
        for (int r = 0; r < 16; r++)
            lg[r * 64 + tid] = red[tid * 16 + r] + red[(tid + 64) * 16 + r] +
                               red[(tid + 128) * 16 + r] + red[(tid + 192) * 16 + r] + gb[tid];
    }
    __syncthreads();
    if (tid < 16) {
        int t = t0 + tid;
        float l0 = -1e30f, l1 = -1e30f;
        int e0 = 0, e1 = 0;
        for (int k = 0; k < E; k++) {
            float l = lg[tid * 64 + k];
            if (l > l0)      { l1 = l0; e1 = e0; l0 = l; e0 = k; }
            else if (l > l1) { l1 = l;  e1 = k; }
        }
        float rr = expf(l1 - l0);
        float w0 = 1.f / (1.f + rr);
        float w1 = rr * w0;
        g_sel[2 * t] = e0;  g_sel[2 * t + 1] = e1;
        g_w[2 * t]   = w0;  g_w[2 * t + 1]   = w1;
    }
}

// ---------------- aux: histogram + scan + pad + scatter ----------------
__global__ void __launch_bounds__(256) k_aux() {
    __shared__ int hist[E];
    __shared__ int soff[E+1], stoff[E+1];
    __shared__ int cur[E];
    const int tid = threadIdx.x;
    if (tid < E) hist[tid] = 0;
    __syncthreads();
    for (int i = tid; i < T * TOPK; i += 256) atomicAdd(&hist[g_sel[i]], 1);
    __syncthreads();
    if (tid == 0) {
        int off = 0, toff = 0;
        for (int e = 0; e < E; e++) {
            soff[e] = off; stoff[e] = toff;
            int tiles = (hist[e] + TMTOK - 1) / TMTOK;
            for (int q = 0; q < tiles; q++) g_texp[toff + q] = e;
            off += tiles * TMTOK; toff += tiles;
        }
        soff[E] = off; stoff[E] = toff;
    }
    __syncthreads();
    if (tid < E) { cur[tid] = soff[tid]; g_off[tid] = soff[tid]; g_tile_off[tid] = stoff[tid]; }
    if (tid == 0) { g_off[E] = soff[E]; g_tile_off[E] = stoff[E]; }
    for (int i = tid; i < PPOS; i += 256) g_perm[i] = -1;
    __syncthreads();
    for (int i = tid; i < T * TOPK; i += 256) {
        int e = g_sel[i];
        int pos = atomicAdd(&cur[e], 1);
        g_perm[pos] = i >> 1;
        g_pw[pos] = g_w[i];
        int local = pos - soff[e];
        g_ypos[i] = (stoff[e] + (local >> 6)) * TMTOK + (local & 63);
    }
}

// ---------------- FFN GEMMs: M64 tiles, 3 CTAs/SM ----------------
#define KC      32
#define RSTRIDE 80
#define STAGE   (256*RSTRIDE)     // 20480 B
#define SMEM_REQ (2*STAGE)        // 40960 B

__device__ __forceinline__ uint32_t adr(uint32_t buf, int rowbase, int ks, int lane) {
    return buf + (uint32_t)(rowbase + (lane & 15)) * RSTRIDE + (uint32_t)(ks * 2 + (lane >> 4)) * 16;
}

// g1 stage rows (64B): [0,64)xh [64,128)xl [128,192)w1 [192,256)w3
__device__ __forceinline__ void ld_g1(uint32_t buf, const int* s_tok, int e, int nc, int k) {
    const int row = threadIdx.x;
    const char* src;
    if (row < 128) {
        int tok = s_tok[row & 63];
        if (tok < 0) tok = T;
        const char* base = (row < 64) ? (const char*)g_xh : (const char*)g_xl;
        src = base + (size_t)tok * (H * 2) + k * (KC * 2);
    } else {
        int n = row & 63;
        const char* base = (row < 192) ? (const char*)g_w1h : (const char*)g_w3h;
        src = base + ((size_t)(e * IDIM + nc * 64 + n)) * (H * 2) + k * (KC * 2);
    }
    uint32_t d = buf + (uint32_t)row * RSTRIDE;
#pragma unroll
    for (int q = 0; q < 4; q++) cpa16(d + q * 16, src + q * 16);
}
// g2 stage rows: [0,64)ah [64,128)al [128,256)w2
__device__ __forceinline__ void ld_g2(uint32_t buf, int tile, int e, int nc, int k) {
    const int row = threadIdx.x;
    const char* src;
    if (row < 128) {
        const char* base = (row < 64) ? (const char*)g_ah32 : (const char*)g_al32;
        src = base + ((size_t)tile * TMTOK + (row & 63)) * (IDIM * 2) + k * (KC * 2);
    } else {
        int n = row - 128;
        src = (const char*)g_w2h + ((size_t)(e * H + nc * 128 + n)) * (IDIM * 2) + k * (KC * 2);
    }
    uint32_t d = buf + (uint32_t)row * RSTRIDE;
#pragma unroll
    for (int q = 0; q < 4; q++) cpa16(d + q * 16, src + q * 16);
}

// ---- GEMM1: h1/h3 for I-chunk of 64. grid (NTILES, 8), M64 ----
__global__ void __launch_bounds__(256, 3) k_g1() {
    const int tile = blockIdx.x;
    if (tile >= g_tile_off[E]) return;
    const int nc = blockIdx.y;
    extern __shared__ char sm[];
    const uint32_t sb = smem_u32(sm);
    __shared__ int   s_tok[TMTOK];
    __shared__ float s_w[TMTOK];

    const int tid = threadIdx.x, lane = tid & 31, wid = tid >> 5;
    const int wm = wid & 1, wn = wid >> 1;   // 2(M) x 4(N): warp M32 x N16 (c1 & c3)

    const int e = g_texp[tile];
    const int p0 = g_off[e] + (tile - g_tile_off[e]) * TMTOK;

    if (tid < TMTOK) {
        int tk = g_perm[p0 + tid];
        s_tok[tid] = tk;
        s_w[tid] = (tk >= 0) ? g_pw[p0 + tid] : 0.f;
    }
    __syncthreads();

    const uint32_t bufs[2] = { sb, sb + STAGE };
    const int rbase = wm * 32 + (lane >> 2);

    ld_g1(bufs[0], s_tok, e, nc, 0); CP_COMMIT();
    float c1[2][2][4], c3[2][2][4];
#pragma unroll
    for (int a = 0; a < 2; a++)
#pragma unroll
        for (int b = 0; b < 2; b++)
#pragma unroll
            for (int c = 0; c < 4; c++) { c1[a][b][c] = 0.f; c3[a][b][c] = 0.f; }

    for (int k = 0; k < 32; k++) {
        CP_WAIT(0);
        __syncthreads();
        if (k + 1 < 32) { ld_g1(bufs[(k + 1) & 1], s_tok, e, nc, k + 1); CP_COMMIT(); }
        uint32_t cb = bufs[k & 1];
#pragma unroll
        for (int ks = 0; ks < 2; ks++) {
            uint32_t ah[2][4], al[2][4];
            ldm4(ah[0], adr(cb, wm * 32,           ks, lane));
            ldm4(ah[1], adr(cb, wm * 32 + 16,      ks, lane));
            ldm4(al[0], adr(cb, 64 + wm * 32,      ks, lane));
            ldm4(al[1], adr(cb, 64 + wm * 32 + 16, ks, lane));
            uint32_t b1[4], b3[4];
            ldm4(b1, adr(cb, 128 + wn * 16, ks, lane));
            ldm4(b3, adr(cb, 192 + wn * 16, ks, lane));
            // term-major fp16 2-term
#pragma unroll
            for (int nk = 0; nk < 2; nk++)
#pragma unroll
                for (int mi = 0; mi < 2; mi++) mma16(c1[mi][nk], ah[mi], b1[nk], b1[nk + 2]);
#pragma unroll
            for (int nk = 0; nk < 2; nk++)
#pragma unroll
                for (int mi = 0; mi < 2; mi++) mma16(c3[mi][nk], ah[mi], b3[nk], b3[nk + 2]);
#pragma unroll
            for (int nk = 0; nk < 2; nk++)
#pragma unroll
                for (int mi = 0; mi < 2; mi++) mma16(c1[mi][nk], al[mi], b1[nk], b1[nk + 2]);
#pragma unroll
            for (int nk = 0; nk < 2; nk++)
#pragma unroll
                for (int mi = 0; mi < 2; mi++) mma16(c3[mi][nk], al[mi], b3[nk], b3[nk + 2]);
        }
    }
    // epilogue: silu(h1)*h3*w -> fp16 hi/lo a-scratch
#pragma unroll
    for (int mi = 0; mi < 2; mi++)
#pragma unroll
        for (int nk = 0; nk < 2; nk++)
#pragma unroll
            for (int hf = 0; hf < 2; hf++) {
                int row = rbase + mi * 16 + hf * 8;
                int col = nc * 64 + wn * 16 + nk * 8 + ((lane & 3) << 1);
                float w = s_w[row];
                float h1a = c1[mi][nk][hf * 2], h1b = c1[mi][nk][hf * 2 + 1];
                float a0 = h1a / (1.f + __expf(-h1a)) * c3[mi][nk][hf * 2] * w;
                float a1 = h1b / (1.f + __expf(-h1b)) * c3[mi][nk][hf * 2 + 1] * w;
                uint32_t hv, lv; split2h(a0, a1, hv, lv);
                size_t o = ((size_t)(tile * TMTOK + row) * IDIM + col) >> 1;
                g_ah32[o] = hv; g_al32[o] = lv;
            }
}

// ---- GEMM2: y for H-chunk of 128. grid (NTILES, 8), M64 ----
__global__ void __launch_bounds__(256, 3) k_g2() {
    const int tile = blockIdx.x;
    if (tile >= g_tile_off[E]) return;
    const int nc = blockIdx.y;
    extern __shared__ char sm[];
    const uint32_t sb = smem_u32(sm);

    const int tid = threadIdx.x, lane = tid & 31, wid = tid >> 5;
    const int wm = wid & 1, wn = wid >> 1;   // 2(M) x 4(N): warp M32 x N32

    const int e = g_texp[tile];
    const uint32_t bufs[2] = { sb, sb + STAGE };
    const int rbase = wm * 32 + (lane >> 2);

    ld_g2(bufs[0], tile, e, nc, 0); CP_COMMIT();
    float cc[2][4][4];
#pragma unroll
    for (int a = 0; a < 2; a++)
#pragma unroll
        for (int b = 0; b < 4; b++)
#pragma unroll
            for (int c = 0; c < 4; c++) cc[a][b][c] = 0.f;

    for (int k = 0; k < 16; k++) {
        CP_WAIT(0);
        __syncthreads();
        if (k + 1 < 16) { ld_g2(bufs[(k + 1) & 1], tile, e, nc, k + 1); CP_COMMIT(); }
        uint32_t cb = bufs[k & 1];
#pragma unroll
        for (int ks = 0; ks < 2; ks++) {
            uint32_t ah[2][4], al[2][4];
            ldm4(ah[0], adr(cb, wm * 32,           ks, lane));
            ldm4(ah[1], adr(cb, wm * 32 + 16,      ks, lane));
            ldm4(al[0], adr(cb, 64 + wm * 32,      ks, lane));
            ldm4(al[1], adr(cb, 64 + wm * 32 + 16, ks, lane));
            uint32_t b2[2][4];
            ldm4(b2[0], adr(cb, 128 + wn * 32,      ks, lane));
            ldm4(b2[1], adr(cb, 128 + wn * 32 + 16, ks, lane));
#pragma unroll
            for (int nj = 0; nj < 2; nj++)
#pragma unroll
                for (int nk = 0; nk < 2; nk++)
#pragma unroll
                    for (int mi = 0; mi < 2; mi++) mma16(cc[mi][nj*2+nk], ah[mi], b2[nj][nk], b2[nj][nk+2]);
#pragma unroll
            for (int nj = 0; nj < 2; nj++)
#pragma unroll
                for (int nk = 0; nk < 2; nk++)
#pragma unroll
                    for (int mi = 0; mi < 2; mi++) mma16(cc[mi][nj*2+nk], al[mi], b2[nj][nk], b2[nj][nk+2]);
        }
    }
#pragma unroll
    for (int mi = 0; mi < 2; mi++)
#pragma unroll
        for (int n4 = 0; n4 < 4; n4++)
#pragma unroll
            for (int hf = 0; hf < 2; hf++) {
                int row = rbase + mi * 16 + hf * 8;
                int col = nc * 128 + wn * 32 + n4 * 8 + ((lane & 3) << 1);
                float2 v = make_float2(cc[mi][n4][hf * 2], cc[mi][n4][hf * 2 + 1]);
                *(float2*)&g_y[(size_t)(tile * TMTOK + row) * H + col] = v;
            }
}

// ---------------- gather ----------------
__global__ void k_gather(float* __restrict__ out) {
    int idx = blockIdx.x * 256 + threadIdx.x;
    if (idx >= T * H / 4) return;
    int t = idx / (H / 4), c = idx % (H / 4);
    int p0 = g_ypos[2 * t], p1 = g_ypos[2 * t + 1];
    float4 a = ((const float4*)g_y)[(size_t)p0 * (H / 4) + c];
    float4 b = ((const float4*)g_y)[(size_t)p1 * (H / 4) + c];
    ((float4*)out)[idx] = make_float4(a.x + b.x, a.y + b.y, a.z + b.z, a.w + b.w);
}

// ---------------- launch ----------------
extern "C" void kernel_launch(void* const* d_in, const int* in_sizes, int n_in,
                              void* d_out, int out_size) {
    const float* x  = (const float*)d_in[0];
    const float* gw = (const float*)d_in[1];
    const float* gb = (const float*)d_in[2];
    const float* W1 = (const float*)d_in[3];
    const float* W2 = (const float*)d_in[4];
    const float* W3 = (const float*)d_in[5];
    float* out = (float*)d_out;

    cudaFuncSetAttribute(k_router, cudaFuncAttributeMaxDynamicSharedMemorySize, 86016);
    cudaFuncSetAttribute(k_g1,     cudaFuncAttributeMaxDynamicSharedMemorySize, SMEM_REQ);
    cudaFuncSetAttribute(k_g2,     cudaFuncAttributeMaxDynamicSharedMemorySize, SMEM_REQ);

    k_cvt<<<2048, 256>>>(x, W1, W2, W3);
    k_router<<<T / 16, 256, 86016>>>(x, gw, gb);
    k_aux<<<1, 256>>>();
    k_g1<<<dim3(NTILES, 8), 256, SMEM_REQ>>>();
    k_g2<<<dim3(NTILES, 8), 256, SMEM_REQ>>>();
    k_gather<<<(T * H / 4 + 255) / 256, 256>>>(out);
}